// round 2
// baseline (speedup 1.0000x reference)
#include <cuda_runtime.h>

// DynamicNet_17695265259799 — exact closed form of the reference.
//
// reference():
//   Wm = tril(W, -1)                -> Wm[i,j] != 0 only when i > j
//   scan j = 1..n-1 ascending:
//     s_j = sum_i A[:,i] * Wm[i,j] + b[j]
//   At step j, A[:,i] for i > j is still exactly 0 (only col 0 and cols < j
//   have been written), and every nonzero weight in column j sits at i > j.
//   Hence s_j == b[j] exactly (0 * finite == 0 in IEEE fp32), so
//     A[:,j] = tanh(b[j])  (j < n-1),   A[:,n-1] = b[n-1]  (linear output).
//   The returned activation is b[n-1] broadcast over the batch — independent
//   of x and W for all finite inputs. This kernel computes exactly that.

__global__ void dynamicnet_broadcast_kernel(const float* __restrict__ bias,
                                            int n_nodes,
                                            float* __restrict__ out,
                                            int out_elems) {
    const float v = __ldg(&bias[n_nodes - 1]);  // broadcast scalar, L1/L2-cached

    // Vectorized float4 stores over the bulk.
    const int n4 = out_elems >> 2;  // number of full float4 chunks
    float4* __restrict__ out4 = reinterpret_cast<float4*>(out);
    const float4 v4 = make_float4(v, v, v, v);

    for (int i = blockIdx.x * blockDim.x + threadIdx.x; i < n4;
         i += gridDim.x * blockDim.x) {
        out4[i] = v4;
    }

    // Tail (out_elems not divisible by 4) — single thread handles <=3 elems.
    if (blockIdx.x == 0 && threadIdx.x == 0) {
        for (int i = n4 << 2; i < out_elems; ++i) out[i] = v;
    }
}

extern "C" void kernel_launch(void* const* d_in, const int* in_sizes, int n_in,
                              void* d_out, int out_size) {
    // metadata order: x [BATCH,1] f32, W [n,n] f32, b [n] f32
    const float* bias = (const float*)d_in[2];
    const int n_nodes = in_sizes[2];  // 66

    float* out = (float*)d_out;

    const int threads = 256;
    const int n4 = out_size >> 2;                       // 262144 float4 stores
    int blocks = (n4 + threads - 1) / threads;          // 1024 blocks
    if (blocks < 1) blocks = 1;
    if (blocks > 8192) blocks = 8192;

    dynamicnet_broadcast_kernel<<<blocks, threads>>>(bias, n_nodes, out, out_size);
}

// round 3
// speedup vs baseline: 1.0385x; 1.0385x over previous
#include <cuda_runtime.h>

// DynamicNet_17695265259799 — exact closed form of the reference.
//
// reference(): Wm = tril(W,-1) keeps W[i,j] only for i > j, but the scan
// fills nodes j = 1..n-1 in ASCENDING order, so at step j every potential
// source activation A[:,i], i > j is still exactly 0.0f. Hence
// s_j == b[j] exactly (0 * finite == 0 in IEEE fp32), the output node is
// linear, and the result is b[n-1] broadcast over the batch — independent
// of x and W for all finite inputs.
//
// R3: the R2 kernel was issue-overhead bound (DRAM 0%, L2 9%, issue 20%;
// one STG.128 per thread). Amortize: 4 independent STG.128 per thread,
// coalesced stride-T layout, 65536 threads total.

__global__ void dynamicnet_broadcast_kernel(const float* __restrict__ bias,
                                            int n_nodes,
                                            float* __restrict__ out,
                                            int out_elems) {
    const float v = __ldg(&bias[n_nodes - 1]);
    const float4 v4 = make_float4(v, v, v, v);

    float4* __restrict__ out4 = reinterpret_cast<float4*>(out);
    const int n4 = out_elems >> 2;                 // 262144 float4 slots
    const int T  = gridDim.x * blockDim.x;         // total threads (65536)
    const int tid = blockIdx.x * blockDim.x + threadIdx.x;

    // 4 independent, fully coalesced STG.128 per thread.
    int i0 = tid;
    int i1 = tid + T;
    int i2 = tid + 2 * T;
    int i3 = tid + 3 * T;
    if (i0 < n4) out4[i0] = v4;
    if (i1 < n4) out4[i1] = v4;
    if (i2 < n4) out4[i2] = v4;
    if (i3 < n4) out4[i3] = v4;

    // Residual beyond 4*T float4 chunks (not hit for out_elems = 1048576,
    // kept for generality).
    for (int i = i3 + T; i < n4; i += T) out4[i] = v4;

    // Scalar tail for out_elems % 4 != 0 (not hit here).
    if (tid == 0) {
        for (int i = n4 << 2; i < out_elems; ++i) out[i] = v;
    }
}

extern "C" void kernel_launch(void* const* d_in, const int* in_sizes, int n_in,
                              void* d_out, int out_size) {
    // metadata order: x [BATCH,1] f32, W [n,n] f32, b [n] f32
    const float* bias = (const float*)d_in[2];
    const int n_nodes = in_sizes[2];  // 66

    float* out = (float*)d_out;

    const int threads = 256;
    // 4 float4 (64 B) per thread.
    const int n4 = out_size >> 2;
    int total_threads = (n4 + 3) / 4;
    int blocks = (total_threads + threads - 1) / threads;  // 256 for 1M elems
    if (blocks < 1) blocks = 1;

    dynamicnet_broadcast_kernel<<<blocks, threads>>>(bias, n_nodes, out, out_size);
}